// round 10
// baseline (speedup 1.0000x reference)
#include <cuda_runtime.h>
#include <cstdint>

typedef unsigned long long u64;

#define BN      131072          // B*N
#define NPROP   16384
#define BIMG    8
#define TPB     1024            // threads per CTA (one CTA per image)
#define M_ENT   32768           // N*(C-1)
#define RSLOTS  16              // register-resident slots (key+box)
#define TSLOTS  32              // total slots (worst case 32768/1024)
#define MC      64              // merged candidates (32 warps x top-2)
#define HALF_NEG (-5e8f)
#define NMS_ITERS 640
#define DET     320
#define BBOX_CLIP_F 4.135166556742356f

// static device scratch (no allocation allowed; zero-initialized at load)
__device__ float4 g_box  [BIMG * M_ENT];   // clipped boxes by ORIGINAL index
__device__ float4 g_cnbox[BIMG * M_ENT];   // compacted offset boxes
__device__ u64    g_ckey [BIMG * M_ENT];   // compacted packed keys
__device__ int    g_cnt  [BIMG];

__device__ __forceinline__ u64 pack_key(float s, unsigned j)
{
    unsigned fb = __float_as_uint(s);
    fb = (fb & 0x80000000u) ? ~fb : (fb | 0x80000000u);   // sortable float
    return ((u64)fb << 32) | (u64)(0xFFFFFFFFu - j);
}

__device__ __forceinline__ float key_score(u64 k)
{
    unsigned fb = (unsigned)(k >> 32);
    unsigned orig = (fb & 0x80000000u) ? (fb ^ 0x80000000u) : ~fb;
    return __uint_as_float(orig);
}

__device__ __forceinline__ u64 warp_max_u64(u64 k)
{
    unsigned hi = (unsigned)(k >> 32);
    unsigned lo = (unsigned)k;
    unsigned mhi = __reduce_max_sync(0xffffffffu, hi);
    unsigned mlo = __reduce_max_sync(0xffffffffu, (hi == mhi) ? lo : 0u);
    return ((u64)mhi << 32) | mlo;
}

// ---------------------------------------------------------------------------
// Prep: decode + softmax + clip + validity + warp-aggregated compaction
// ---------------------------------------------------------------------------
__global__ void prep_kernel(const float* __restrict__ logits,
                            const float* __restrict__ breg,
                            const float* __restrict__ props)
{
    int g = blockIdx.x * blockDim.x + threadIdx.x;
    if (g >= BN) return;
    int b = g >> 14;
    int n = g & (NPROP - 1);
    int lane = threadIdx.x & 31;

    float l0 = logits[g * 3 + 0];
    float l1 = logits[g * 3 + 1];
    float l2 = logits[g * 3 + 2];
    float mx = fmaxf(l0, fmaxf(l1, l2));
    float e0 = expf(l0 - mx), e1 = expf(l1 - mx), e2 = expf(l2 - mx);
    float sum = e0 + e1 + e2;
    float sc[2] = { e1 / sum, e2 / sum };

    float px1 = props[g * 4 + 0];
    float py1 = props[g * 4 + 1];
    float px2 = props[g * 4 + 2];
    float py2 = props[g * 4 + 3];
    float w  = px2 - px1;
    float h  = py2 - py1;
    float cx = px1 + 0.5f * w;
    float cy = py1 + 0.5f * h;

    const float fs = 1024.0f;

    float4 bx[2], nbx[2];
    bool   valid[2];
    #pragma unroll
    for (int c = 1; c <= 2; c++) {
        float r0 = breg[g * 12 + 4 * c + 0];
        float r1 = breg[g * 12 + 4 * c + 1];
        float r2 = breg[g * 12 + 4 * c + 2];
        float r3 = breg[g * 12 + 4 * c + 3];
        float dx = r0 / 10.0f;
        float dy = r1 / 10.0f;
        float dw = fminf(r2 / 5.0f, BBOX_CLIP_F);
        float dh = fminf(r3 / 5.0f, BBOX_CLIP_F);
        float pcx = dx * w + cx;
        float pcy = dy * h + cy;
        float pw = expf(dw) * w;
        float ph = expf(dh) * h;
        float x1 = pcx - 0.5f * pw;
        float y1 = pcy - 0.5f * ph;
        float x2 = pcx + 0.5f * pw;
        float y2 = pcy + 0.5f * ph;
        x1 = fminf(fmaxf(x1, 0.0f), fs);
        y1 = fminf(fmaxf(y1, 0.0f), fs);
        x2 = fminf(fmaxf(x2, 0.0f), fs);
        y2 = fminf(fmaxf(y2, 0.0f), fs);

        float s = sc[c - 1];
        valid[c - 1] = (s > 0.3f) && ((x2 - x1) >= 0.01f) && ((y2 - y1) >= 0.01f);
        float off = (float)c * (fs + 1.0f);   // 1025 / 2050 (exact)
        bx[c - 1]  = make_float4(x1, y1, x2, y2);
        nbx[c - 1] = make_float4(x1 + off, y1 + off, x2 + off, y2 + off);
    }

    unsigned m1 = __ballot_sync(0xffffffffu, valid[0]);
    unsigned m2 = __ballot_sync(0xffffffffu, valid[1]);
    int basepos = 0;
    if (lane == 0) basepos = atomicAdd(&g_cnt[b], __popc(m1) + __popc(m2));
    basepos = __shfl_sync(0xffffffffu, basepos, 0);
    unsigned lt = (1u << lane) - 1u;

    int obase = b * M_ENT;
    if (valid[0]) {
        int pos = basepos + __popc(m1 & lt);
        unsigned m = 2u * n + 0u;
        g_cnbox[obase + pos] = nbx[0];
        g_ckey [obase + pos] = pack_key(sc[0], m);
        g_box  [obase + m]   = bx[0];
    }
    if (valid[1]) {
        int pos = basepos + __popc(m1) + __popc(m2 & lt);
        unsigned m = 2u * n + 1u;
        g_cnbox[obase + pos] = nbx[1];
        g_ckey [obase + pos] = pack_key(sc[1], m);
        g_box  [obase + m]   = bx[1];
    }
}

// ---------------------------------------------------------------------------
// NMS: ONE CTA per image (1024 thr). Batched greedy selection:
// 32 warps each publish their top-2 (redux chains, no block barriers),
// exact multi-accept walk over 64 merged candidates, batched suppression.
// Only ~4 __syncthreads per round; no cluster anywhere.
// ---------------------------------------------------------------------------
__global__ void __launch_bounds__(TPB, 1)
nms_kernel(float* __restrict__ out)
{
    __shared__ u64      cKey[MC];
    __shared__ float4   cBox[MC];
    __shared__ unsigned sortedIdx[MC];
    __shared__ unsigned rankPos[MC];
    __shared__ u64      conf[MC];
    __shared__ unsigned recIdx[NMS_ITERS];
    __shared__ float    recScore[NMS_ITERS];
    __shared__ int      slots[NMS_ITERS];

    const int t = threadIdx.x;
    const int w = t >> 5;
    const int b = blockIdx.x;
    const int base = b * M_ENT;

    const int cnt = g_cnt[b];

    // owned entries: slots 0..15 register-resident (key+box), 16..31 key-only
    u64    key[TSLOTS];
    float4 nb [RSLOTS];
    #pragma unroll
    for (int e = 0; e < RSLOTS; e++) {
        int c = e * TPB + t;
        if (c < cnt) {
            key[e] = g_ckey [base + c];
            nb[e]  = g_cnbox[base + c];
        } else {
            key[e] = 0ull;
            nb[e]  = make_float4(0.f, 0.f, 0.f, 0.f);
        }
    }
    const bool overflow = cnt > RSLOTS * TPB;   // uniform; false for this data
    #pragma unroll
    for (int e = RSLOTS; e < TSLOTS; e++) {
        int c = e * TPB + t;
        key[e] = (overflow && c < cnt) ? g_ckey[base + c] : 0ull;
    }

    int selCount = 0;

    for (int round = 0; round < NMS_ITERS; ++round) {
        // ---- 1. per-warp top-2 extraction (no block barriers) -------------
        u64 lmax = 0ull;
        #pragma unroll
        for (int e = 0; e < TSLOTS; e++)
            if (key[e] > lmax) lmax = key[e];

        bool sentA = false, sentB = false;
        int  slotA = 0,  slotB = 0;
        u64  kvalA = 0,  kvalB = 0;

        // pick 1
        u64 k1 = warp_max_u64(lmax);
        if (k1 != 0ull) {
            if (lmax == k1) {              // unique winner lane
                float4 wb = make_float4(0.f, 0.f, 0.f, 0.f);
                int ws = -1;
                #pragma unroll
                for (int e = 0; e < RSLOTS; e++)
                    if (key[e] == k1) { wb = nb[e]; ws = e; }
                if (overflow && ws < 0) {
                    #pragma unroll
                    for (int e = RSLOTS; e < TSLOTS; e++)
                        if (key[e] == k1) ws = e;
                    wb = g_cnbox[base + ws * TPB + t];
                }
                #pragma unroll
                for (int e = 0; e < TSLOTS; e++)
                    if (key[e] == k1) key[e] = 0ull;
                cKey[w * 2] = k1;
                cBox[w * 2] = wb;
                sentA = true; slotA = ws; kvalA = k1;
                lmax = 0ull;
                #pragma unroll
                for (int e = 0; e < TSLOTS; e++)
                    if (key[e] > lmax) lmax = key[e];
            }
        } else if ((t & 31) == 0) {
            cKey[w * 2] = 0ull;
            cBox[w * 2] = make_float4(0.f, 0.f, 0.f, 0.f);
        }

        // pick 2
        u64 k2 = warp_max_u64(lmax);
        if (k2 != 0ull) {
            if (lmax == k2) {
                float4 wb = make_float4(0.f, 0.f, 0.f, 0.f);
                int ws = -1;
                #pragma unroll
                for (int e = 0; e < RSLOTS; e++)
                    if (key[e] == k2) { wb = nb[e]; ws = e; }
                if (overflow && ws < 0) {
                    #pragma unroll
                    for (int e = RSLOTS; e < TSLOTS; e++)
                        if (key[e] == k2) ws = e;
                    wb = g_cnbox[base + ws * TPB + t];
                }
                #pragma unroll
                for (int e = 0; e < TSLOTS; e++)
                    if (key[e] == k2) key[e] = 0ull;
                cKey[w * 2 + 1] = k2;
                cBox[w * 2 + 1] = wb;
                sentB = true; slotB = ws; kvalB = k2;
            }
        } else if ((t & 31) == 0) {
            cKey[w * 2 + 1] = 0ull;
            cBox[w * 2 + 1] = make_float4(0.f, 0.f, 0.f, 0.f);
        }
        __syncthreads();                                   // barrier 1

        // ---- 2. sort merged 64 by key desc (t<64), clear conf -------------
        if (t < MC) {
            u64 km = cKey[t];
            unsigned pos = 0;
            #pragma unroll
            for (int m2 = 0; m2 < MC; m2++) {
                u64 kk = cKey[m2];
                pos += (kk > km) || (kk == km && m2 < t);
            }
            rankPos[t] = pos;
            sortedIdx[pos] = (unsigned)t;
            conf[t] = 0ull;
        }
        __syncthreads();                                   // barrier 2

        // pool empty? (uniform)
        if (cKey[sortedIdx[0]] == 0ull) break;

        // T = max over warps of their 2nd sent key (withheld keys < this)
        u64 Tk = 0ull;
        #pragma unroll
        for (int ww = 0; ww < 32; ww++) {
            u64 ks = cKey[ww * 2 + 1];
            if (ks > Tk) Tk = ks;
        }

        // ---- 3. conflict matrix in sorted space ---------------------------
        {
            int j = t >> 4;              // 64 rows x 16 threads
            int sub = t & 15;
            int i0 = sub * 4;
            int i1 = i0 + 4; if (i1 > j) i1 = j;
            if (i0 < i1) {
                unsigned mj = sortedIdx[j];
                u64 kj = cKey[mj];
                if (kj != 0ull) {
                    float4 bj = cBox[mj];
                    float aj = (bj.z - bj.x) * (bj.w - bj.y);
                    u64 m = 0ull;
                    for (int i = i0; i < i1; i++) {
                        unsigned mi = sortedIdx[i];
                        float4 bi = cBox[mi];
                        float ai = (bi.z - bi.x) * (bi.w - bi.y);
                        float ltx = fmaxf(bi.x, bj.x);
                        float lty = fmaxf(bi.y, bj.y);
                        float rbx = fminf(bi.z, bj.z);
                        float rby = fminf(bi.w, bj.w);
                        float iw = fmaxf(rbx - ltx, 0.0f);
                        float ih = fmaxf(rby - lty, 0.0f);
                        float inter = iw * ih;
                        float iou = inter / (ai + aj - inter);
                        if (iou > 0.3f) m |= 1ull << i;
                    }
                    if (m) atomicOr(&conf[j], m);
                }
            }
        }
        __syncthreads();                                   // barrier 3

        // ---- 4. resolve walk (redundant; uniform) -------------------------
        u64 acc = 0ull;
        int P_eff = MC;
        {
            int c0 = selCount;
            for (int j = 0; j < MC; j++) {
                unsigned mj = sortedIdx[j];
                u64 kj = cKey[mj];
                if (kj == 0ull || kj < Tk) { P_eff = j; break; }
                if (c0 == NMS_ITERS)       { P_eff = j; break; }
                if ((conf[j] & acc) == 0ull) {
                    acc |= 1ull << j;
                    if (t == 0) {
                        recIdx[c0]   = 0xFFFFFFFFu - (unsigned)kj;
                        recScore[c0] = key_score(kj);
                    }
                    c0++;
                }
            }
            selCount = c0;
        }

        // ---- 5. restore own unprocessed candidates (static idx) -----------
        if (sentA && rankPos[w * 2] >= (unsigned)P_eff) {
            #pragma unroll
            for (int e = 0; e < TSLOTS; e++)
                if (e == slotA) key[e] = kvalA;
        }
        if (sentB && rankPos[w * 2 + 1] >= (unsigned)P_eff) {
            #pragma unroll
            for (int e = 0; e < TSLOTS; e++)
                if (e == slotB) key[e] = kvalB;
        }

        // ---- 6. batched suppression (slot-outer, winners-inner) -----------
        #pragma unroll
        for (int e = 0; e < RSLOTS; e++) {
            if (key[e] != 0ull) {
                float ae = (nb[e].z - nb[e].x) * (nb[e].w - nb[e].y);
                u64 rem = acc;
                while (rem) {
                    int j = __ffsll((long long)rem) - 1;
                    rem &= rem - 1;
                    unsigned mj = sortedIdx[j];
                    float4 wb4 = cBox[mj];
                    float a1 = (wb4.z - wb4.x) * (wb4.w - wb4.y);
                    float ltx = fmaxf(wb4.x, nb[e].x);
                    float lty = fmaxf(wb4.y, nb[e].y);
                    float rbx = fminf(wb4.z, nb[e].z);
                    float rby = fminf(wb4.w, nb[e].w);
                    float iw = fmaxf(rbx - ltx, 0.0f);
                    float ih = fmaxf(rby - lty, 0.0f);
                    float inter = iw * ih;
                    float iou = inter / (a1 + ae - inter);
                    if (iou > 0.3f) { key[e] = 0ull; break; }
                }
            }
        }
        if (overflow) {
            #pragma unroll
            for (int e = RSLOTS; e < TSLOTS; e++) {
                if (key[e] != 0ull) {
                    float4 c4 = g_cnbox[base + e * TPB + t];
                    float ae = (c4.z - c4.x) * (c4.w - c4.y);
                    u64 rem = acc;
                    while (rem) {
                        int j = __ffsll((long long)rem) - 1;
                        rem &= rem - 1;
                        unsigned mj = sortedIdx[j];
                        float4 wb4 = cBox[mj];
                        float a1 = (wb4.z - wb4.x) * (wb4.w - wb4.y);
                        float ltx = fmaxf(wb4.x, c4.x);
                        float lty = fmaxf(wb4.y, c4.y);
                        float rbx = fminf(wb4.z, c4.z);
                        float rby = fminf(wb4.w, c4.w);
                        float iw = fmaxf(rbx - ltx, 0.0f);
                        float ih = fmaxf(rby - lty, 0.0f);
                        float inter = iw * ih;
                        float iou = inter / (a1 + ae - inter);
                        if (iou > 0.3f) { key[e] = 0ull; break; }
                    }
                }
            }
        }

        if (selCount >= NMS_ITERS) break;
        __syncthreads();                                   // barrier 4
    }

    // ------------------- epilogue ------------------------------------------
    __syncthreads();

    const int nRec = selCount;
    float* oBoxes  = out;                         // [8][320][4]
    float* oScores = out + BIMG * DET * 4;        // [8][320]
    float* oLabels = out + BIMG * DET * 5;        // [8][320]

    for (int q = t; q < DET * 4; q += TPB) oBoxes[b * DET * 4 + q] = 0.0f;
    for (int q = t; q < DET;     q += TPB) { oScores[b * DET + q] = 0.0f; oLabels[b * DET + q] = 0.0f; }

    if (t == 0) {
        int c0 = 0;
        for (int r = 0; r < nRec; r++)
            if (recScore[r] > HALF_NEG && (recIdx[r] & 1u)) c0++;
        int p0 = 0, p1 = 0;
        for (int r = 0; r < nRec; r++) {
            bool ok = recScore[r] > HALF_NEG;
            int slot = -1;
            if (ok) slot = (recIdx[r] & 1u) ? (p0++) : (c0 + p1++);
            slots[r] = slot;
        }
    }
    __syncthreads();

    for (int q = t; q < nRec; q += TPB) {
        int slot = slots[q];
        if (slot >= 0 && slot < DET) {
            unsigned i = recIdx[q];
            float4 bx = g_box[base + i];
            float* dst = oBoxes + (b * DET + slot) * 4;
            dst[0] = bx.x; dst[1] = bx.y; dst[2] = bx.z; dst[3] = bx.w;
            oScores[b * DET + slot] = recScore[q];
            oLabels[b * DET + slot] = (float)((i & 1u) + 1u);
        }
    }

    if (t == 0) g_cnt[b] = 0;   // self-clean for next graph replay
}

// ---------------------------------------------------------------------------
extern "C" void kernel_launch(void* const* d_in, const int* in_sizes, int n_in,
                              void* d_out, int out_size)
{
    (void)in_sizes; (void)n_in; (void)out_size;
    const float* logits = (const float*)d_in[0];
    const float* breg   = (const float*)d_in[1];
    const float* props  = (const float*)d_in[2];
    float* out = (float*)d_out;

    prep_kernel<<<BN / 256, 256>>>(logits, breg, props);
    nms_kernel<<<BIMG, TPB>>>(out);
}

// round 12
// speedup vs baseline: 13.9192x; 13.9192x over previous
#include <cuda_runtime.h>
#include <cstdint>

typedef unsigned long long u64;

#define BN      131072          // B*N
#define NPROP   16384
#define BIMG    8
#define NM      32768           // entries per image (incl. invalid)
#define CHUNK   256
#define DET     320
#define NMS_ITERS 640
#define BBOX_CLIP_F 4.135166556742356f

// static device scratch (no allocation allowed)
__device__ float4 g_box [BIMG * NM];   // clipped boxes by original m (valid only)
__device__ float4 g_nbox[BIMG * NM];   // offset boxes by original m (valid only)
__device__ u64    g_skey[BIMG * NM];   // keys (0 invalid); sorted desc in place

__device__ __forceinline__ u64 pack_key(float s, unsigned j)
{
    unsigned fb = __float_as_uint(s);
    fb = (fb & 0x80000000u) ? ~fb : (fb | 0x80000000u);   // sortable float
    return ((u64)fb << 32) | (u64)(0xFFFFFFFFu - j);
}

__device__ __forceinline__ float key_score(u64 k)
{
    unsigned fb = (unsigned)(k >> 32);
    unsigned orig = (fb & 0x80000000u) ? (fb ^ 0x80000000u) : ~fb;
    return __uint_as_float(orig);
}

// ---------------------------------------------------------------------------
// Prep: decode + softmax + clip + validity; key for EVERY m (0 if invalid)
// ---------------------------------------------------------------------------
__global__ void prep_kernel(const float* __restrict__ logits,
                            const float* __restrict__ breg,
                            const float* __restrict__ props)
{
    int g = blockIdx.x * blockDim.x + threadIdx.x;
    if (g >= BN) return;
    int b = g >> 14;
    int n = g & (NPROP - 1);

    float l0 = logits[g * 3 + 0];
    float l1 = logits[g * 3 + 1];
    float l2 = logits[g * 3 + 2];
    float mx = fmaxf(l0, fmaxf(l1, l2));
    float e0 = expf(l0 - mx), e1 = expf(l1 - mx), e2 = expf(l2 - mx);
    float sum = e0 + e1 + e2;
    float sc[2] = { e1 / sum, e2 / sum };

    float px1 = props[g * 4 + 0];
    float py1 = props[g * 4 + 1];
    float px2 = props[g * 4 + 2];
    float py2 = props[g * 4 + 3];
    float w  = px2 - px1;
    float h  = py2 - py1;
    float cx = px1 + 0.5f * w;
    float cy = py1 + 0.5f * h;

    const float fs = 1024.0f;

    #pragma unroll
    for (int c = 1; c <= 2; c++) {
        float r0 = breg[g * 12 + 4 * c + 0];
        float r1 = breg[g * 12 + 4 * c + 1];
        float r2 = breg[g * 12 + 4 * c + 2];
        float r3 = breg[g * 12 + 4 * c + 3];
        float dx = r0 / 10.0f;
        float dy = r1 / 10.0f;
        float dw = fminf(r2 / 5.0f, BBOX_CLIP_F);
        float dh = fminf(r3 / 5.0f, BBOX_CLIP_F);
        float pcx = dx * w + cx;
        float pcy = dy * h + cy;
        float pw = expf(dw) * w;
        float ph = expf(dh) * h;
        float x1 = pcx - 0.5f * pw;
        float y1 = pcy - 0.5f * ph;
        float x2 = pcx + 0.5f * pw;
        float y2 = pcy + 0.5f * ph;
        x1 = fminf(fmaxf(x1, 0.0f), fs);
        y1 = fminf(fmaxf(y1, 0.0f), fs);
        x2 = fminf(fmaxf(x2, 0.0f), fs);
        y2 = fminf(fmaxf(y2, 0.0f), fs);

        float s = sc[c - 1];
        bool valid = (s > 0.3f) && ((x2 - x1) >= 0.01f) && ((y2 - y1) >= 0.01f);
        float off = (float)c * (fs + 1.0f);   // 1025 / 2050 (exact)
        unsigned m = 2u * (unsigned)n + (unsigned)(c - 1);
        int o = b * NM + (int)m;
        g_skey[o] = valid ? pack_key(s, m) : 0ull;
        if (valid) {
            g_box [o] = make_float4(x1, y1, x2, y2);
            g_nbox[o] = make_float4(x1 + off, y1 + off, x2 + off, y2 + off);
        }
    }
}

// ---------------------------------------------------------------------------
// Bitonic sort (descending) per image, n = 32768. 4096-element smem tiles.
// desc comparison at stage k for in-image index i iff (i & k) == 0.
// ---------------------------------------------------------------------------
__global__ void __launch_bounds__(512, 1) sort_tileA()
{
    __shared__ u64 sk[4096];
    const int t = threadIdx.x;
    const int img  = blockIdx.x >> 3;
    const int tile = blockIdx.x & 7;
    const int gb = img * NM + tile * 4096;
    const int wb = tile * 4096;

    #pragma unroll
    for (int i = t; i < 4096; i += 512) sk[i] = g_skey[gb + i];
    __syncthreads();

    for (int k = 2; k <= 4096; k <<= 1) {
        for (int s = k >> 1; s > 0; s >>= 1) {
            for (int q = t; q < 2048; q += 512) {
                int i = (q << 1) - (q & (s - 1));
                int l = i + s;
                bool desc = (((wb + i) & k) == 0);
                u64 a = sk[i], c = sk[l];
                bool sw = desc ? (a < c) : (a > c);
                if (sw) { sk[i] = c; sk[l] = a; }
            }
            __syncthreads();
        }
    }
    #pragma unroll
    for (int i = t; i < 4096; i += 512) g_skey[gb + i] = sk[i];
}

__global__ void __launch_bounds__(512, 2) sort_gstep(int k, int s)
{
    int p = blockIdx.x * blockDim.x + threadIdx.x;   // 8 * 16384 pairs
    int img = p >> 14;
    int pl  = p & 16383;
    int i = (pl << 1) - (pl & (s - 1));
    u64* a = g_skey + img * NM;
    bool desc = ((i & k) == 0);
    u64 x = a[i], y = a[i + s];
    bool sw = desc ? (x < y) : (x > y);
    if (sw) { a[i] = y; a[i + s] = x; }
}

__global__ void __launch_bounds__(512, 1) sort_tileS(int k)
{
    __shared__ u64 sk[4096];
    const int t = threadIdx.x;
    const int img  = blockIdx.x >> 3;
    const int tile = blockIdx.x & 7;
    const int gb = img * NM + tile * 4096;
    const bool desc = (((tile * 4096) & k) == 0);    // uniform: k >= 8192

    #pragma unroll
    for (int i = t; i < 4096; i += 512) sk[i] = g_skey[gb + i];
    __syncthreads();

    for (int s = 2048; s > 0; s >>= 1) {
        for (int q = t; q < 2048; q += 512) {
            int i = (q << 1) - (q & (s - 1));
            int l = i + s;
            u64 a = sk[i], c = sk[l];
            bool sw = desc ? (a < c) : (a > c);
            if (sw) { sk[i] = c; sk[l] = a; }
        }
        __syncthreads();
    }
    #pragma unroll
    for (int i = t; i < 4096; i += 512) g_skey[gb + i] = sk[i];
}

// ---------------------------------------------------------------------------
// Walk: one CTA per image, all state in smem. Chunks of 256 sorted keys.
// Exact greedy: sorted order IS selection order; conflict-mask resolve.
// ---------------------------------------------------------------------------
__global__ void __launch_bounds__(1024, 1) walk_kernel(float* __restrict__ out)
{
    __shared__ u64      candKey[CHUNK];
    __shared__ float4   candBox[CHUNK];
    __shared__ float    candArea[CHUNK];
    __shared__ u64      killmask[CHUNK][4];
    __shared__ unsigned dead32[CHUNK / 32];
    __shared__ float4   selBox[NMS_ITERS];
    __shared__ float    selArea[NMS_ITERS];
    __shared__ unsigned recIdx[NMS_ITERS];
    __shared__ float    recScore[NMS_ITERS];
    __shared__ int      slots[NMS_ITERS];

    const int t = threadIdx.x;
    const int b = blockIdx.x;
    const int base = b * NM;

    int selCount = 0;

    for (int chunk = 0; chunk < NM / CHUNK; ++chunk) {
        // ---- phase A: load chunk, derive dead-from-invalid, clear masks ----
        u64 myk = 0ull;
        if (t < CHUNK) {
            myk = g_skey[base + chunk * CHUNK + t];
            candKey[t] = myk;
            if (myk != 0ull) {
                unsigned m = 0xFFFFFFFFu - (unsigned)myk;
                float4 bb = g_nbox[base + (int)m];
                candBox[t]  = bb;
                candArea[t] = (bb.z - bb.x) * (bb.w - bb.y);
            }
            unsigned bal = __ballot_sync(0xffffffffu, myk == 0ull);
            if ((t & 31) == 0) dead32[t >> 5] = bal;
        }
        killmask[t >> 2][t & 3] = 0ull;
        __syncthreads();

        // ---- phase B: kill vs already-selected (atomicOr dead32) ----------
        {
            int j = t & (CHUNK - 1);
            u64 ck = candKey[j];
            if (ck != 0ull) {
                float4 cb = candBox[j];
                float ca = candArea[j];
                for (int s = t >> 8; s < selCount; s += 4) {
                    float4 sb = selBox[s];
                    float ltx = fmaxf(sb.x, cb.x);
                    float lty = fmaxf(sb.y, cb.y);
                    float rbx = fminf(sb.z, cb.z);
                    float rby = fminf(sb.w, cb.w);
                    float iw = fmaxf(rbx - ltx, 0.0f);
                    float ih = fmaxf(rby - lty, 0.0f);
                    float inter = iw * ih;
                    float iou = inter / (selArea[s] + ca - inter);
                    if (iou > 0.3f) {
                        atomicOr(&dead32[j >> 5], 1u << (j & 31));
                        break;
                    }
                }
            }
        }
        // ---- phase C (same region): intra-chunk conflict matrix -----------
        {
            int jr  = t >> 2;
            int sub = t & 3;
            int i0 = sub * 64;
            int i1 = i0 + 64; if (i1 > jr) i1 = jr;
            if (i0 < i1 && candKey[jr] != 0ull) {
                float4 bj = candBox[jr];
                float aj = candArea[jr];
                u64 m = 0ull;
                for (int i = i0; i < i1; i++) {
                    float4 bi = candBox[i];
                    float ai = candArea[i];
                    float ltx = fmaxf(bi.x, bj.x);
                    float lty = fmaxf(bi.y, bj.y);
                    float rbx = fminf(bi.z, bj.z);
                    float rby = fminf(bi.w, bj.w);
                    float iw = fmaxf(rbx - ltx, 0.0f);
                    float ih = fmaxf(rby - lty, 0.0f);
                    float inter = iw * ih;
                    float iou = inter / (ai + aj - inter);   // winner area first
                    if (iou > 0.3f) m |= 1ull << (i & 63);
                }
                killmask[jr][sub] = m;                       // unique writer
            }
        }
        __syncthreads();

        // ---- phase D: resolve (redundant, uniform) ------------------------
        u64 d0 = (u64)dead32[0] | ((u64)dead32[1] << 32);
        u64 d1 = (u64)dead32[2] | ((u64)dead32[3] << 32);
        u64 d2 = (u64)dead32[4] | ((u64)dead32[5] << 32);
        u64 d3 = (u64)dead32[6] | ((u64)dead32[7] << 32);
        u64 acc0 = 0, acc1 = 0, acc2 = 0, acc3 = 0;
        int c0 = selCount;
        bool full = false;

#define RESOLVE_WORD(W, dW, accW)                                             \
        if (!full) for (int jj = 0; jj < 64; jj++) {                          \
            if (((dW >> jj) & 1ull) == 0ull) {                                \
                int j = (W << 6) | jj;                                        \
                u64 h = (killmask[j][0] & acc0) | (killmask[j][1] & acc1)     \
                      | (killmask[j][2] & acc2) | (killmask[j][3] & acc3);    \
                if (h == 0ull) {                                              \
                    if (c0 < NMS_ITERS) { accW |= (1ull << jj); c0++; }       \
                    else { full = true; break; }                              \
                }                                                             \
            }                                                                 \
        }
        RESOLVE_WORD(0, d0, acc0)
        RESOLVE_WORD(1, d1, acc1)
        RESOLVE_WORD(2, d2, acc2)
        RESOLVE_WORD(3, d3, acc3)
#undef RESOLVE_WORD

        // ---- append accepted (threads t<256; ranks from popcounts) --------
        if (t < CHUNK) {
            int jw = t >> 6, jj = t & 63;
            u64 aw = (jw == 0) ? acc0 : (jw == 1) ? acc1 : (jw == 2) ? acc2 : acc3;
            if ((aw >> jj) & 1ull) {
                int rank = selCount;
                if (jw > 0) rank += __popcll(acc0);
                if (jw > 1) rank += __popcll(acc1);
                if (jw > 2) rank += __popcll(acc2);
                rank += __popcll(aw & ((1ull << jj) - 1ull));
                selBox[rank]  = candBox[t];
                selArea[rank] = candArea[t];
                u64 kk = candKey[t];
                recIdx[rank]   = 0xFFFFFFFFu - (unsigned)kk;
                recScore[rank] = key_score(kk);
            }
        }
        selCount = c0;
        __syncthreads();

        // uniform exits: key stream exhausted (sorted: zeros at end) or cap
        if (candKey[CHUNK - 1] == 0ull) break;
        if (selCount >= NMS_ITERS) break;
    }

    // ------------------- epilogue ------------------------------------------
    const int nRec = selCount;
    float* oBoxes  = out;                         // [8][320][4]
    float* oScores = out + BIMG * DET * 4;        // [8][320]
    float* oLabels = out + BIMG * DET * 5;        // [8][320]

    for (int q = t; q < DET * 4; q += 1024) oBoxes[b * DET * 4 + q] = 0.0f;
    for (int q = t; q < DET;     q += 1024) { oScores[b * DET + q] = 0.0f; oLabels[b * DET + q] = 0.0f; }

    if (t == 0) {
        int c2 = 0;
        for (int r = 0; r < nRec; r++)
            if (recIdx[r] & 1u) c2++;             // label-2 entries (m odd)
        int p0 = 0, p1 = 0;
        for (int r = 0; r < nRec; r++) {
            int slot = (recIdx[r] & 1u) ? (p0++) : (c2 + p1++);
            slots[r] = slot;
        }
    }
    __syncthreads();

    for (int q = t; q < nRec; q += 1024) {
        int slot = slots[q];
        if (slot < DET) {
            unsigned i = recIdx[q];
            float4 bx = g_box[base + (int)i];
            float* dst = oBoxes + (b * DET + slot) * 4;
            dst[0] = bx.x; dst[1] = bx.y; dst[2] = bx.z; dst[3] = bx.w;
            oScores[b * DET + slot] = recScore[q];
            oLabels[b * DET + slot] = (float)((i & 1u) + 1u);
        }
    }
}

// ---------------------------------------------------------------------------
extern "C" void kernel_launch(void* const* d_in, const int* in_sizes, int n_in,
                              void* d_out, int out_size)
{
    (void)in_sizes; (void)n_in; (void)out_size;
    const float* logits = (const float*)d_in[0];
    const float* breg   = (const float*)d_in[1];
    const float* props  = (const float*)d_in[2];
    float* out = (float*)d_out;

    prep_kernel<<<BN / 256, 256>>>(logits, breg, props);

    sort_tileA<<<BIMG * 8, 512>>>();
    // stage k = 8192
    sort_gstep<<<256, 512>>>(8192, 4096);
    sort_tileS<<<BIMG * 8, 512>>>(8192);
    // stage k = 16384
    sort_gstep<<<256, 512>>>(16384, 8192);
    sort_gstep<<<256, 512>>>(16384, 4096);
    sort_tileS<<<BIMG * 8, 512>>>(16384);
    // stage k = 32768
    sort_gstep<<<256, 512>>>(32768, 16384);
    sort_gstep<<<256, 512>>>(32768, 8192);
    sort_gstep<<<256, 512>>>(32768, 4096);
    sort_tileS<<<BIMG * 8, 512>>>(32768);

    walk_kernel<<<BIMG, 1024>>>(out);
}